// round 8
// baseline (speedup 1.0000x reference)
#include <cuda_runtime.h>
#include <cuda_bf16.h>

// ---------------- problem constants (fixed by the dataset) ----------------
#define NN      100000      // total nodes
#define HH      64          // hidden features
#define EE      800000      // edges per edge set
#define GG      50000       // ground nodes (ground_node = arange(N) < G)
#define NGRAPH  128
#define FIN     32
#define NBUK    21          // degree buckets 0..20 (bucket 0 <=> deg==0 <=> passthrough)
#define LN_EPS  1e-5f

#define M2      256                       // nodes per apply block
#define CH2     ((NN + M2 - 1) / M2)      // 391 chunks
// dynamic smem: sA[128][256] + sWd[128][128] + sBLd[128]
#define AP2_SMEM ((128*256 + 128*128 + 128) * 4)

// ---------------- scratch (static device globals; no allocation) ----------
__device__ float g_h  [NN * HH];
__device__ float g_h0 [NN * HH];
__device__ float g_hs [NN * HH];
__device__ int   g_deg4[4 * NN];
__device__ int   g_cnt4[4 * NBUK];
__device__ int   g_list4[4 * NBUK * NN];
__device__ float g_pooled[NGRAPH * HH];

// vector f32 reduction (PTX ISA 8.1+, sm_90+): 1 L2 atomic op for 16B
__device__ __forceinline__ void red_add_v4(float* p, float4 v) {
    asm volatile("red.global.add.v4.f32 [%0], {%1, %2, %3, %4};"
                 :: "l"(p), "f"(v.x), "f"(v.y), "f"(v.z), "f"(v.w) : "memory");
}

// packed fp32x2 FMA (Blackwell; only reachable via PTX)
__device__ __forceinline__ unsigned long long ffma2(unsigned long long a,
                                                    unsigned long long b,
                                                    unsigned long long c) {
    unsigned long long d;
    asm("fma.rn.f32x2 %0, %1, %2, %3;" : "=l"(d) : "l"(a), "l"(b), "l"(c));
    return d;
}
__device__ __forceinline__ float lo32(unsigned long long v) {
    return __uint_as_float((unsigned)v);
}
__device__ __forceinline__ float hi32(unsigned long long v) {
    return __uint_as_float((unsigned)(v >> 32));
}

struct __align__(16) U2 { unsigned long long x, y; };

// ---------------- K1: embedding  h = x @ emb_w + emb_b ; h0 = h ----------
__global__ void k_embed(const float* __restrict__ x,
                        const float* __restrict__ w,
                        const float* __restrict__ b) {
    __shared__ float sw[FIN * HH];
    __shared__ float sb[HH];
    for (int i = threadIdx.x; i < FIN * HH; i += 256) sw[i] = w[i];
    if (threadIdx.x < HH) sb[threadIdx.x] = b[threadIdx.x];
    __syncthreads();

    int n = blockIdx.x * 256 + threadIdx.x;
    if (n >= NN) return;

    float xv[FIN];
    const float4* xp = reinterpret_cast<const float4*>(x + n * FIN);
#pragma unroll
    for (int q = 0; q < FIN / 4; q++) {
        float4 v = xp[q];
        xv[q*4+0] = v.x; xv[q*4+1] = v.y; xv[q*4+2] = v.z; xv[q*4+3] = v.w;
    }

#pragma unroll
    for (int cc = 0; cc < 4; cc++) {
        float acc[16];
#pragma unroll
        for (int c = 0; c < 16; c++) acc[c] = sb[cc*16 + c];
#pragma unroll
        for (int k = 0; k < FIN; k++) {
            float xk = xv[k];
#pragma unroll
            for (int c = 0; c < 16; c++) acc[c] += xk * sw[k*HH + cc*16 + c];
        }
        float4* ho  = reinterpret_cast<float4*>(g_h  + n*HH + cc*16);
        float4* h0o = reinterpret_cast<float4*>(g_h0 + n*HH + cc*16);
#pragma unroll
        for (int q = 0; q < 4; q++) {
            float4 v = make_float4(acc[q*4], acc[q*4+1], acc[q*4+2], acc[q*4+3]);
            ho[q] = v; h0o[q] = v;
        }
    }
}

// ---------------- prologue A: degree count for all 4 edge sets ------------
__global__ void k_deg(const int* __restrict__ d0, const int* __restrict__ d1,
                      const int* __restrict__ d2, const int* __restrict__ d3) {
    int e = blockIdx.x * 256 + threadIdx.x;
    if (e >= EE) return;
    int j = blockIdx.y;
    const int* d = (j == 0) ? d0 : (j == 1) ? d1 : (j == 2) ? d2 : d3;
    atomicAdd(&g_deg4[j * NN + d[e]], 1);
}

// ---------------- prologue B: bucket lists for all 4 edge sets ------------
// fixed-size segments per bucket (NN each) -> no scan needed
__global__ void k_fill4() {
    __shared__ int scnt[NBUK], sbase[NBUK], scur[NBUK];
    int t = threadIdx.x;
    int j = blockIdx.y;
    if (t < NBUK) { scnt[t] = 0; scur[t] = 0; }
    __syncthreads();
    int i = blockIdx.x * 256 + t;
    int b = -1;
    if (i < NN) {
        int d = g_deg4[j * NN + i];
        b = d < NBUK - 1 ? d : NBUK - 1;
        atomicAdd(&scnt[b], 1);
    }
    __syncthreads();
    if (t < NBUK && scnt[t] > 0) sbase[t] = atomicAdd(&g_cnt4[j * NBUK + t], scnt[t]);
    __syncthreads();
    if (i < NN) {
        int pos = atomicAdd(&scur[b], 1);
        g_list4[(j * NBUK + b) * NN + sbase[b] + pos] = i;
    }
}

// ---------------- K2: scatter  hs[dst] += h[src] ------------------------
__global__ void k_scatter(const int* __restrict__ src, const int* __restrict__ dst) {
    int t = blockIdx.x * 256 + threadIdx.x;
    int e = t >> 4;
    if (e >= EE) return;
    int c = t & 15;
    int s = src[e];
    int d = dst[e];
    float4 v = *reinterpret_cast<const float4*>(&g_h[s * HH + c * 4]);
    red_add_v4(&g_hs[d * HH + c * 4], v);
}

// ---------------- K6: bucketed apply, FFMA2 path -------------------------
// out = [hs,h] @ [wl;wr] + bl  as one K=128 GEMM per bucket.
// block: 256 nodes, 128 threads, thread tile = 16 nodes (8 f32x2 pairs) x 8 cols.
__global__ void __launch_bounds__(128, 1)
k_apply2(const float* __restrict__ wl_base,
         const float* __restrict__ bl_base,
         const float* __restrict__ wr_base,
         int relu, int j) {
    int b = blockIdx.y;
    int cnt = g_cnt4[j * NBUK + b];
    int chunk0 = blockIdx.x * M2;
    if (chunk0 >= cnt) return;
    const int* list = g_list4 + (j * NBUK + b) * NN + chunk0;
    int nv = cnt - chunk0; if (nv > M2) nv = M2;
    int tid = threadIdx.x;

    if (b == 0) {                       // deg==0: h unchanged, relu still applies
        if (!relu) return;
        for (int idx = tid; idx < nv * 16; idx += 128) {
            int n = list[idx >> 4];
            int c = (idx & 15) * 4;
            float4* p = reinterpret_cast<float4*>(&g_h[n * HH + c]);
            float4 v = *p;
            v.x = fmaxf(v.x, 0.f); v.y = fmaxf(v.y, 0.f);
            v.z = fmaxf(v.z, 0.f); v.w = fmaxf(v.w, 0.f);
            *p = v;
        }
        return;
    }

    extern __shared__ float sm[];
    float* sA   = sm;                       // [k=0..127][m=0..255]
    float* sWd  = sm + 128 * 256;           // [k=0..127][2*col] duplicated {w,w}
    float* sBLd = sm + 128 * 256 + 128 * 128; // duplicated bias, 128 floats

    const float* wl = wl_base + b * HH * HH;
    const float* wr = wr_base + b * HH * HH;
    const float* bl = bl_base + b * HH;

    // stage weights duplicated: rows 0..63 = wl, 64..127 = wr
    for (int i = tid; i < 1024; i += 128) {      // float4 index over 64x64
        int k  = i >> 4;
        int n4 = (i & 15) * 4;
        float4 v = reinterpret_cast<const float4*>(wl)[i];
        float4* dst = reinterpret_cast<float4*>(&sWd[k * 128 + 2 * n4]);
        dst[0] = make_float4(v.x, v.x, v.y, v.y);
        dst[1] = make_float4(v.z, v.z, v.w, v.w);
        v = reinterpret_cast<const float4*>(wr)[i];
        dst = reinterpret_cast<float4*>(&sWd[(k + 64) * 128 + 2 * n4]);
        dst[0] = make_float4(v.x, v.x, v.y, v.y);
        dst[1] = make_float4(v.z, v.z, v.w, v.w);
    }
    if (tid < HH) { float v = bl[tid]; sBLd[2*tid] = v; sBLd[2*tid+1] = v; }

    // stage activations transposed: sA[k][m] = hs[node_m][k] (k<64) / h (k>=64)
#pragma unroll
    for (int rep = 0; rep < 2; rep++) {
        int m = tid + rep * 128;
        int node = (m < nv) ? list[m] : -1;
        const float4* ha = (node >= 0) ? reinterpret_cast<const float4*>(&g_hs[node * HH]) : nullptr;
        const float4* hb = (node >= 0) ? reinterpret_cast<const float4*>(&g_h [node * HH]) : nullptr;
#pragma unroll
        for (int q = 0; q < 16; q++) {
            float4 va = (node >= 0) ? ha[q] : make_float4(0.f, 0.f, 0.f, 0.f);
            float4 vb = (node >= 0) ? hb[q] : make_float4(0.f, 0.f, 0.f, 0.f);
            int k0 = q * 4;
            sA[(k0+0)*M2 + m] = va.x; sA[(k0+1)*M2 + m] = va.y;
            sA[(k0+2)*M2 + m] = va.z; sA[(k0+3)*M2 + m] = va.w;
            sA[(64+k0+0)*M2 + m] = vb.x; sA[(64+k0+1)*M2 + m] = vb.y;
            sA[(64+k0+2)*M2 + m] = vb.z; sA[(64+k0+3)*M2 + m] = vb.w;
        }
    }
    __syncthreads();

    int tx = tid & 7;          // col group: cols tx*8 .. tx*8+7
    int ty = tid >> 3;         // node group: nodes ty*16 .. ty*16+15 (8 pairs)
    int m0 = ty * 16;

    unsigned long long acc[8][8];
    {
        const unsigned long long* blp =
            reinterpret_cast<const unsigned long long*>(sBLd + tx * 16);
        unsigned long long bv[8];
#pragma unroll
        for (int c = 0; c < 8; c++) bv[c] = blp[c];
#pragma unroll
        for (int p = 0; p < 8; p++)
#pragma unroll
            for (int c = 0; c < 8; c++) acc[p][c] = bv[c];
    }

#pragma unroll 4
    for (int k = 0; k < 128; k++) {
        const U2* ap = reinterpret_cast<const U2*>(sA + k * M2 + m0);
        const U2* wp = reinterpret_cast<const U2*>(sWd + k * 128 + tx * 16);
        U2 a0 = ap[0], a1 = ap[1], a2 = ap[2], a3 = ap[3];
        U2 w0 = wp[0], w1 = wp[1], w2 = wp[2], w3 = wp[3];
        unsigned long long av[8] = {a0.x, a0.y, a1.x, a1.y, a2.x, a2.y, a3.x, a3.y};
        unsigned long long wv[8] = {w0.x, w0.y, w1.x, w1.y, w2.x, w2.y, w3.x, w3.y};
#pragma unroll
        for (int p = 0; p < 8; p++) {
            unsigned long long a = av[p];
#pragma unroll
            for (int c = 0; c < 8; c++)
                acc[p][c] = ffma2(a, wv[c], acc[p][c]);
        }
    }

    // epilogue: pair p holds nodes (m0+2p, m0+2p+1) in (lo, hi) lanes
#pragma unroll
    for (int p = 0; p < 8; p++) {
        int m = m0 + 2 * p;
        if (m < nv) {
            int node = list[m];
            float4 v0 = make_float4(lo32(acc[p][0]), lo32(acc[p][1]),
                                    lo32(acc[p][2]), lo32(acc[p][3]));
            float4 v1 = make_float4(lo32(acc[p][4]), lo32(acc[p][5]),
                                    lo32(acc[p][6]), lo32(acc[p][7]));
            if (relu) {
                v0.x = fmaxf(v0.x, 0.f); v0.y = fmaxf(v0.y, 0.f);
                v0.z = fmaxf(v0.z, 0.f); v0.w = fmaxf(v0.w, 0.f);
                v1.x = fmaxf(v1.x, 0.f); v1.y = fmaxf(v1.y, 0.f);
                v1.z = fmaxf(v1.z, 0.f); v1.w = fmaxf(v1.w, 0.f);
            }
            float4* o = reinterpret_cast<float4*>(&g_h[node * HH + tx * 8]);
            o[0] = v0; o[1] = v1;
        }
        if (m + 1 < nv) {
            int node = list[m + 1];
            float4 v0 = make_float4(hi32(acc[p][0]), hi32(acc[p][1]),
                                    hi32(acc[p][2]), hi32(acc[p][3]));
            float4 v1 = make_float4(hi32(acc[p][4]), hi32(acc[p][5]),
                                    hi32(acc[p][6]), hi32(acc[p][7]));
            if (relu) {
                v0.x = fmaxf(v0.x, 0.f); v0.y = fmaxf(v0.y, 0.f);
                v0.z = fmaxf(v0.z, 0.f); v0.w = fmaxf(v0.w, 0.f);
                v1.x = fmaxf(v1.x, 0.f); v1.y = fmaxf(v1.y, 0.f);
                v1.z = fmaxf(v1.z, 0.f); v1.w = fmaxf(v1.w, 0.f);
            }
            float4* o = reinterpret_cast<float4*>(&g_h[node * HH + tx * 8]);
            o[0] = v0; o[1] = v1;
        }
    }
}

// ---------------- K7: LayerNorm + residual --------------------------------
__global__ void k_ln(const float* __restrict__ g, const float* __restrict__ bb) {
    int wid = (blockIdx.x * 256 + threadIdx.x) >> 5;
    int lane = threadIdx.x & 31;
    if (wid >= NN) return;
    const float* hp = g_h + wid * HH;
    float v0 = hp[lane], v1 = hp[lane + 32];
    float s = v0 + v1;
#pragma unroll
    for (int o = 16; o > 0; o >>= 1) s += __shfl_xor_sync(0xffffffffu, s, o);
    float mu = s * (1.f / 64.f);
    float d0 = v0 - mu, d1 = v1 - mu;
    float q = d0 * d0 + d1 * d1;
#pragma unroll
    for (int o = 16; o > 0; o >>= 1) q += __shfl_xor_sync(0xffffffffu, q, o);
    float rstd = rsqrtf(q * (1.f / 64.f) + LN_EPS);
    const float* h0p = g_h0 + wid * HH;
    g_h[wid*HH + lane]      = d0 * rstd * g[lane]      + bb[lane]      + h0p[lane];
    g_h[wid*HH + lane + 32] = d1 * rstd * g[lane + 32] + bb[lane + 32] + h0p[lane + 32];
}

// ---------------- K8: pooled[batch[i]] += h[i] for ground nodes (i<G) -----
__global__ void k_pool(const int* __restrict__ batch_idx) {
    int t = blockIdx.x * 256 + threadIdx.x;
    int i = t >> 4;
    if (i >= GG) return;
    int c = (t & 15) * 4;
    int gidx = batch_idx[i];
    float4 v = *reinterpret_cast<const float4*>(&g_h[i * HH + c]);
    red_add_v4(&g_pooled[gidx * HH + c], v);
}

// ---------------- K9: out = pooled @ out_w + out_b ------------------------
__global__ void k_out(const float* __restrict__ ow, const float* __restrict__ ob,
                      float* __restrict__ out) {
    int gidx = threadIdx.x;           // 128 threads
    float acc = ob[0];
#pragma unroll
    for (int k = 0; k < HH; k++) acc += g_pooled[gidx * HH + k] * ow[k];
    out[gidx] = acc;
}

// ---------------- host launcher ------------------------------------------
extern "C" void kernel_launch(void* const* d_in, const int* in_sizes, int n_in,
                              void* d_out, int out_size) {
    (void)in_sizes; (void)n_in; (void)out_size;
    const float* x        = (const float*)d_in[0];
    // reference edge-set order: edge_index, node_subnode, subgraph_edge, subnode_node
    const int* eis[4] = { (const int*)d_in[1], (const int*)d_in[3],
                          (const int*)d_in[2], (const int*)d_in[4] };
    const int*   batch_idx = (const int*)d_in[7];
    const float* emb_w  = (const float*)d_in[8];
    const float* emb_b  = (const float*)d_in[9];
    const float* conv_wl = (const float*)d_in[10];
    const float* conv_bl = (const float*)d_in[11];
    const float* conv_wr = (const float*)d_in[12];
    const float* ln_g   = (const float*)d_in[13];
    const float* ln_b   = (const float*)d_in[14];
    const float* out_w  = (const float*)d_in[15];
    const float* out_b  = (const float*)d_in[16];
    float* out = (float*)d_out;

    void *p_hs, *p_deg4, *p_cnt4, *p_pooled;
    cudaGetSymbolAddress(&p_hs, g_hs);
    cudaGetSymbolAddress(&p_deg4, g_deg4);
    cudaGetSymbolAddress(&p_cnt4, g_cnt4);
    cudaGetSymbolAddress(&p_pooled, g_pooled);

    cudaFuncSetAttribute(k_apply2, cudaFuncAttributeMaxDynamicSharedMemorySize,
                         AP2_SMEM);

    // ---- prologue: structure-only bucketing for all 4 edge sets ----
    cudaMemsetAsync(p_deg4, 0, sizeof(int) * 4 * NN);
    cudaMemsetAsync(p_cnt4, 0, sizeof(int) * 4 * NBUK);
    {
        dim3 gd((EE + 255) / 256, 4);
        k_deg<<<gd, 256>>>(eis[0] + EE, eis[1] + EE, eis[2] + EE, eis[3] + EE);
        dim3 gf((NN + 255) / 256, 4);
        k_fill4<<<gf, 256>>>();
    }

    k_embed<<<(NN + 255) / 256, 256>>>(x, emb_w, emb_b);

    for (int j = 0; j < 4; j++) {
        cudaMemsetAsync(p_hs, 0, sizeof(float) * NN * HH);
        k_scatter<<<(EE * 16 + 255) / 256, 256>>>(eis[j], eis[j] + EE);
        dim3 grid(CH2, NBUK);
        k_apply2<<<grid, 128, AP2_SMEM>>>(conv_wl + j * NBUK * HH * HH,
                                          conv_bl + j * NBUK * HH,
                                          conv_wr + j * NBUK * HH * HH,
                                          (j < 3) ? 1 : 0, j);
    }

    k_ln<<<(NN * 32 + 255) / 256, 256>>>(ln_g, ln_b);

    cudaMemsetAsync(p_pooled, 0, sizeof(float) * NGRAPH * HH);
    k_pool<<<(GG * 16 + 255) / 256, 256>>>(batch_idx);
    k_out<<<1, NGRAPH>>>(out_w, out_b, out);
}

// round 9
// speedup vs baseline: 1.4275x; 1.4275x over previous
#include <cuda_runtime.h>
#include <cuda_bf16.h>

// ---------------- problem constants (fixed by the dataset) ----------------
#define NN      100000      // total nodes
#define HH      64          // hidden features
#define EE      800000      // edges per edge set
#define GG      50000       // ground nodes (ground_node = arange(N) < G)
#define NGRAPH  128
#define FIN     32
#define NBUK    21          // degree buckets 0..20 (bucket 0 <=> deg==0 <=> passthrough)
#define NPB     64          // nodes per apply-GEMM block
#define LN_EPS  1e-5f
#define WORKMAX 1600        // >= ceil(NN/NPB) + NBUK

// ---------------- scratch (static device globals; no allocation) ----------
__device__ float g_h  [NN * HH];
__device__ float g_h0 [NN * HH];
__device__ float g_hs [NN * HH];
__device__ int   g_deg4 [4 * NN];
__device__ int   g_cnt4 [4 * NBUK];
__device__ int   g_list4[4 * NBUK * NN];
__device__ int   g_work [4 * WORKMAX];
__device__ int   g_nwork[4];
__device__ float g_pooled[NGRAPH * HH];

// vector f32 reduction (PTX ISA 8.1+, sm_90+): 1 L2 atomic op for 16B
__device__ __forceinline__ void red_add_v4(float* p, float4 v) {
    asm volatile("red.global.add.v4.f32 [%0], {%1, %2, %3, %4};"
                 :: "l"(p), "f"(v.x), "f"(v.y), "f"(v.z), "f"(v.w) : "memory");
}

// ---------------- K1: embedding  h = x @ emb_w + emb_b ; h0 = h ----------
__global__ void k_embed(const float* __restrict__ x,
                        const float* __restrict__ w,
                        const float* __restrict__ b) {
    __shared__ float sw[FIN * HH];
    __shared__ float sb[HH];
    for (int i = threadIdx.x; i < FIN * HH; i += 256) sw[i] = w[i];
    if (threadIdx.x < HH) sb[threadIdx.x] = b[threadIdx.x];
    __syncthreads();

    int n = blockIdx.x * 256 + threadIdx.x;
    if (n >= NN) return;

    float xv[FIN];
    const float4* xp = reinterpret_cast<const float4*>(x + n * FIN);
#pragma unroll
    for (int q = 0; q < FIN / 4; q++) {
        float4 v = xp[q];
        xv[q*4+0] = v.x; xv[q*4+1] = v.y; xv[q*4+2] = v.z; xv[q*4+3] = v.w;
    }

#pragma unroll
    for (int cc = 0; cc < 4; cc++) {
        float acc[16];
#pragma unroll
        for (int c = 0; c < 16; c++) acc[c] = sb[cc*16 + c];
#pragma unroll
        for (int k = 0; k < FIN; k++) {
            float xk = xv[k];
#pragma unroll
            for (int c = 0; c < 16; c++) acc[c] += xk * sw[k*HH + cc*16 + c];
        }
        float4* ho  = reinterpret_cast<float4*>(g_h  + n*HH + cc*16);
        float4* h0o = reinterpret_cast<float4*>(g_h0 + n*HH + cc*16);
#pragma unroll
        for (int q = 0; q < 4; q++) {
            float4 v = make_float4(acc[q*4], acc[q*4+1], acc[q*4+2], acc[q*4+3]);
            ho[q] = v; h0o[q] = v;
        }
    }
}

// ---------------- prologue A: degree count for all 4 edge sets ------------
__global__ void k_deg(const int* __restrict__ d0, const int* __restrict__ d1,
                      const int* __restrict__ d2, const int* __restrict__ d3) {
    int e = blockIdx.x * 256 + threadIdx.x;
    if (e >= EE) return;
    int j = blockIdx.y;
    const int* d = (j == 0) ? d0 : (j == 1) ? d1 : (j == 2) ? d2 : d3;
    atomicAdd(&g_deg4[j * NN + d[e]], 1);
}

// ---------------- prologue B: bucket lists for all 4 edge sets ------------
// fixed NN-sized segments per bucket -> no global scan needed
__global__ void k_fill4() {
    __shared__ int scnt[NBUK], sbase[NBUK], scur[NBUK];
    int t = threadIdx.x;
    int j = blockIdx.y;
    if (t < NBUK) { scnt[t] = 0; scur[t] = 0; }
    __syncthreads();
    int i = blockIdx.x * 256 + t;
    int b = -1;
    if (i < NN) {
        int d = g_deg4[j * NN + i];
        b = d < NBUK - 1 ? d : NBUK - 1;
        atomicAdd(&scnt[b], 1);
    }
    __syncthreads();
    if (t < NBUK && scnt[t] > 0) sbase[t] = atomicAdd(&g_cnt4[j * NBUK + t], scnt[t]);
    __syncthreads();
    if (i < NN) {
        int pos = atomicAdd(&scur[b], 1);
        g_list4[(j * NBUK + b) * NN + sbase[b] + pos] = i;
    }
}

// ---------------- prologue C: compact (bucket,chunk) work lists -----------
__global__ void k_work() {          // grid = 4 blocks (one per edge set)
    int j = blockIdx.x;
    __shared__ int soff[NBUK + 1];
    if (threadIdx.x == 0) {
        int run = 0;
        for (int b = 0; b < NBUK; b++) {
            soff[b] = run;
            run += (g_cnt4[j * NBUK + b] + NPB - 1) / NPB;
        }
        soff[NBUK] = run;
        g_nwork[j] = run;
    }
    __syncthreads();
    for (int b = 0; b < NBUK; b++) {
        int nch = soff[b + 1] - soff[b];
        for (int c = threadIdx.x; c < nch; c += blockDim.x)
            g_work[j * WORKMAX + soff[b] + c] = (b << 16) | c;
    }
}

// ---------------- K2: scatter  hs[dst] += h[src]  (2 edges / thread) ------
__global__ void k_scatter(const int* __restrict__ src, const int* __restrict__ dst) {
    int t = blockIdx.x * 256 + threadIdx.x;
    int e0 = t >> 4;
    if (e0 >= EE / 2) return;
    int c = (t & 15) * 4;
    int e1 = e0 + EE / 2;
    // front-batch all loads for MLP
    int s0 = src[e0], d0 = dst[e0];
    int s1 = src[e1], d1 = dst[e1];
    float4 v0 = *reinterpret_cast<const float4*>(&g_h[s0 * HH + c]);
    float4 v1 = *reinterpret_cast<const float4*>(&g_h[s1 * HH + c]);
    red_add_v4(&g_hs[d0 * HH + c], v0);
    red_add_v4(&g_hs[d1 * HH + c], v1);
}

// ---------------- K6: bucketed apply (scalar 4x4 tiles, compact grid) -----
// out = hs @ wl[d] + h @ wr[d] + bl[d]; bucket 0 passthrough (+optional relu)
// grid.x = WORKMAX, 256 threads, dynamic smem:
//   sWL[4096] sWR[4096] sA[4096] sB[4096] sBL[64]  -> 65792 bytes (3 CTA/SM)
#define APPLY_SMEM ((4096 * 4 + 64) * 4)

__global__ void k_apply(const float* __restrict__ wl_base,
                        const float* __restrict__ bl_base,
                        const float* __restrict__ wr_base,
                        int relu, int j) {
    if ((int)blockIdx.x >= g_nwork[j]) return;
    int item = g_work[j * WORKMAX + blockIdx.x];
    int b = item >> 16;
    int chunk0 = (item & 0xffff) * NPB;
    int cnt = g_cnt4[j * NBUK + b];
    const int* list = g_list4 + (j * NBUK + b) * NN + chunk0;
    int nvalid = cnt - chunk0; if (nvalid > NPB) nvalid = NPB;
    int tid = threadIdx.x;

    if (b == 0) {                       // deg==0: h unchanged, relu still applies
        if (!relu) return;
        for (int idx = tid; idx < nvalid * 16; idx += 256) {
            int n = list[idx >> 4];
            int c = (idx & 15) * 4;
            float4* p = reinterpret_cast<float4*>(&g_h[n * HH + c]);
            float4 v = *p;
            v.x = fmaxf(v.x, 0.f); v.y = fmaxf(v.y, 0.f);
            v.z = fmaxf(v.z, 0.f); v.w = fmaxf(v.w, 0.f);
            *p = v;
        }
        return;
    }

    extern __shared__ float smem[];
    float* sWL = smem;
    float* sWR = smem + 4096;
    float* sA  = smem + 8192;   // hs^T: [k][m]
    float* sB  = smem + 12288;  // h^T : [k][m]
    float* sBL = smem + 16384;

    const float* wl = wl_base + b * HH * HH;
    const float* wr = wr_base + b * HH * HH;
    const float* bl = bl_base + b * HH;

    for (int i = tid; i < 1024; i += 256) {
        reinterpret_cast<float4*>(sWL)[i] = reinterpret_cast<const float4*>(wl)[i];
        reinterpret_cast<float4*>(sWR)[i] = reinterpret_cast<const float4*>(wr)[i];
    }
    if (tid < HH) sBL[tid] = bl[tid];

    // stage activations transposed: sA[k][m] = hs[node_m][k]
    {
        int m  = tid & 63;
        int kq = tid >> 6;                 // 0..3, each covers 16 k's
        int node = (m < nvalid) ? list[m] : -1;
#pragma unroll
        for (int q = 0; q < 4; q++) {
            int k0 = kq * 16 + q * 4;
            float4 va = make_float4(0.f, 0.f, 0.f, 0.f), vb = va;
            if (node >= 0) {
                va = *reinterpret_cast<const float4*>(&g_hs[node * HH + k0]);
                vb = *reinterpret_cast<const float4*>(&g_h [node * HH + k0]);
            }
            sA[(k0+0)*64 + m] = va.x; sA[(k0+1)*64 + m] = va.y;
            sA[(k0+2)*64 + m] = va.z; sA[(k0+3)*64 + m] = va.w;
            sB[(k0+0)*64 + m] = vb.x; sB[(k0+1)*64 + m] = vb.y;
            sB[(k0+2)*64 + m] = vb.z; sB[(k0+3)*64 + m] = vb.w;
        }
    }
    __syncthreads();

    int tx4 = (tid & 15) * 4;   // output cols
    int ty4 = (tid >> 4) * 4;   // nodes
    float acc[4][4];
#pragma unroll
    for (int i = 0; i < 4; i++)
#pragma unroll
        for (int j2 = 0; j2 < 4; j2++) acc[i][j2] = sBL[tx4 + j2];

#pragma unroll 8
    for (int k = 0; k < HH; k++) {
        float4 a  = *reinterpret_cast<const float4*>(&sA [k*64 + ty4]);
        float4 hh = *reinterpret_cast<const float4*>(&sB [k*64 + ty4]);
        float4 wl4 = *reinterpret_cast<const float4*>(&sWL[k*64 + tx4]);
        float4 wr4 = *reinterpret_cast<const float4*>(&sWR[k*64 + tx4]);
        float av[4] = {a.x, a.y, a.z, a.w};
        float hv[4] = {hh.x, hh.y, hh.z, hh.w};
        float lv[4] = {wl4.x, wl4.y, wl4.z, wl4.w};
        float rv[4] = {wr4.x, wr4.y, wr4.z, wr4.w};
#pragma unroll
        for (int i = 0; i < 4; i++)
#pragma unroll
            for (int j2 = 0; j2 < 4; j2++)
                acc[i][j2] += av[i] * lv[j2] + hv[i] * rv[j2];
    }

#pragma unroll
    for (int i = 0; i < 4; i++) {
        int m = (tid >> 4) * 4 + i;
        if (m < nvalid) {
            int node = list[m];
            float4 o = make_float4(acc[i][0], acc[i][1], acc[i][2], acc[i][3]);
            if (relu) {
                o.x = fmaxf(o.x, 0.f); o.y = fmaxf(o.y, 0.f);
                o.z = fmaxf(o.z, 0.f); o.w = fmaxf(o.w, 0.f);
            }
            *reinterpret_cast<float4*>(&g_h[node * HH + tx4]) = o;
        }
    }
}

// ---------------- K7: LayerNorm + residual --------------------------------
__global__ void k_ln(const float* __restrict__ g, const float* __restrict__ bb) {
    int wid = (blockIdx.x * 256 + threadIdx.x) >> 5;
    int lane = threadIdx.x & 31;
    if (wid >= NN) return;
    const float* hp = g_h + wid * HH;
    float v0 = hp[lane], v1 = hp[lane + 32];
    float s = v0 + v1;
#pragma unroll
    for (int o = 16; o > 0; o >>= 1) s += __shfl_xor_sync(0xffffffffu, s, o);
    float mu = s * (1.f / 64.f);
    float d0 = v0 - mu, d1 = v1 - mu;
    float q = d0 * d0 + d1 * d1;
#pragma unroll
    for (int o = 16; o > 0; o >>= 1) q += __shfl_xor_sync(0xffffffffu, q, o);
    float rstd = rsqrtf(q * (1.f / 64.f) + LN_EPS);
    const float* h0p = g_h0 + wid * HH;
    g_h[wid*HH + lane]      = d0 * rstd * g[lane]      + bb[lane]      + h0p[lane];
    g_h[wid*HH + lane + 32] = d1 * rstd * g[lane + 32] + bb[lane + 32] + h0p[lane + 32];
}

// ---------------- K8: pooled[batch[i]] += h[i] for ground nodes (i<G) -----
__global__ void k_pool(const int* __restrict__ batch_idx) {
    int t = blockIdx.x * 256 + threadIdx.x;
    int i = t >> 4;
    if (i >= GG) return;
    int c = (t & 15) * 4;
    int gidx = batch_idx[i];
    float4 v = *reinterpret_cast<const float4*>(&g_h[i * HH + c]);
    red_add_v4(&g_pooled[gidx * HH + c], v);
}

// ---------------- K9: out = pooled @ out_w + out_b ------------------------
__global__ void k_out(const float* __restrict__ ow, const float* __restrict__ ob,
                      float* __restrict__ out) {
    int gidx = threadIdx.x;           // 128 threads
    float acc = ob[0];
#pragma unroll
    for (int k = 0; k < HH; k++) acc += g_pooled[gidx * HH + k] * ow[k];
    out[gidx] = acc;
}

// ---------------- host launcher ------------------------------------------
extern "C" void kernel_launch(void* const* d_in, const int* in_sizes, int n_in,
                              void* d_out, int out_size) {
    (void)in_sizes; (void)n_in; (void)out_size;
    const float* x        = (const float*)d_in[0];
    // reference edge-set order: edge_index, node_subnode, subgraph_edge, subnode_node
    const int* eis[4] = { (const int*)d_in[1], (const int*)d_in[3],
                          (const int*)d_in[2], (const int*)d_in[4] };
    const int*   batch_idx = (const int*)d_in[7];
    const float* emb_w  = (const float*)d_in[8];
    const float* emb_b  = (const float*)d_in[9];
    const float* conv_wl = (const float*)d_in[10];
    const float* conv_bl = (const float*)d_in[11];
    const float* conv_wr = (const float*)d_in[12];
    const float* ln_g   = (const float*)d_in[13];
    const float* ln_b   = (const float*)d_in[14];
    const float* out_w  = (const float*)d_in[15];
    const float* out_b  = (const float*)d_in[16];
    float* out = (float*)d_out;

    void *p_hs, *p_deg4, *p_cnt4, *p_pooled;
    cudaGetSymbolAddress(&p_hs, g_hs);
    cudaGetSymbolAddress(&p_deg4, g_deg4);
    cudaGetSymbolAddress(&p_cnt4, g_cnt4);
    cudaGetSymbolAddress(&p_pooled, g_pooled);

    cudaFuncSetAttribute(k_apply, cudaFuncAttributeMaxDynamicSharedMemorySize,
                         APPLY_SMEM);

    // ---- prologue: structure-only bucketing + work lists (all 4 edge sets)
    cudaMemsetAsync(p_deg4, 0, sizeof(int) * 4 * NN);
    cudaMemsetAsync(p_cnt4, 0, sizeof(int) * 4 * NBUK);
    {
        dim3 gd((EE + 255) / 256, 4);
        k_deg<<<gd, 256>>>(eis[0] + EE, eis[1] + EE, eis[2] + EE, eis[3] + EE);
        dim3 gf((NN + 255) / 256, 4);
        k_fill4<<<gf, 256>>>();
        k_work<<<4, 256>>>();
    }

    k_embed<<<(NN + 255) / 256, 256>>>(x, emb_w, emb_b);

    for (int j = 0; j < 4; j++) {
        cudaMemsetAsync(p_hs, 0, sizeof(float) * NN * HH);
        k_scatter<<<(EE * 8 + 255) / 256, 256>>>(eis[j], eis[j] + EE);
        k_apply<<<WORKMAX, 256, APPLY_SMEM>>>(conv_wl + j * NBUK * HH * HH,
                                              conv_bl + j * NBUK * HH,
                                              conv_wr + j * NBUK * HH * HH,
                                              (j < 3) ? 1 : 0, j);
    }

    k_ln<<<(NN * 32 + 255) / 256, 256>>>(ln_g, ln_b);

    cudaMemsetAsync(p_pooled, 0, sizeof(float) * NGRAPH * HH);
    k_pool<<<(GG * 16 + 255) / 256, 256>>>(batch_idx);
    k_out<<<1, NGRAPH>>>(out_w, out_b, out);
}

// round 10
// speedup vs baseline: 1.4402x; 1.0090x over previous
#include <cuda_runtime.h>
#include <cuda_bf16.h>

// ---------------- problem constants (fixed by the dataset) ----------------
#define NN      100000      // total nodes
#define HH      64          // hidden features
#define EE      800000      // edges per edge set
#define GG      50000       // ground nodes (ground_node = arange(N) < G)
#define NGRAPH  128
#define FIN     32
#define NBUK    21          // degree buckets 0..20 (bucket 0 <=> deg==0 <=> passthrough)
#define NPB     128         // nodes per apply-GEMM block
#define LN_EPS  1e-5f
#define WORKMAX 832         // >= ceil(NN/NPB) + NBUK

// ---------------- scratch (static device globals; no allocation) ----------
__device__ float g_h  [NN * HH];
__device__ float g_h0 [NN * HH];
__device__ float g_hs [NN * HH];
__device__ int   g_deg4 [4 * NN];
__device__ int   g_cnt4 [4 * NBUK];
__device__ int   g_list4[4 * NBUK * NN];
__device__ int   g_work [4 * WORKMAX];
__device__ int   g_nwork[4];
__device__ float g_pooled[NGRAPH * HH];

// vector f32 reduction (PTX ISA 8.1+, sm_90+): 1 L2 atomic op for 16B
__device__ __forceinline__ void red_add_v4(float* p, float4 v) {
    asm volatile("red.global.add.v4.f32 [%0], {%1, %2, %3, %4};"
                 :: "l"(p), "f"(v.x), "f"(v.y), "f"(v.z), "f"(v.w) : "memory");
}

// packed fp32x2 FMA (Blackwell; only reachable via PTX)
__device__ __forceinline__ unsigned long long ffma2(unsigned long long a,
                                                    unsigned long long b,
                                                    unsigned long long c) {
    unsigned long long d;
    asm("fma.rn.f32x2 %0, %1, %2, %3;" : "=l"(d) : "l"(a), "l"(b), "l"(c));
    return d;
}
__device__ __forceinline__ unsigned long long dup2(float v) {
    unsigned u = __float_as_uint(v);
    unsigned long long r;
    asm("mov.b64 %0, {%1, %1};" : "=l"(r) : "r"(u));
    return r;
}
__device__ __forceinline__ float lo32(unsigned long long v) {
    return __uint_as_float((unsigned)v);
}
__device__ __forceinline__ float hi32(unsigned long long v) {
    return __uint_as_float((unsigned)(v >> 32));
}
struct __align__(16) U2 { unsigned long long x, y; };

// ---------------- K1: embedding  h = x @ emb_w + emb_b ; h0 = h ----------
// x staged via padded smem so per-thread regs stay low (occupancy)
__global__ void k_embed(const float* __restrict__ x,
                        const float* __restrict__ w,
                        const float* __restrict__ b) {
    __shared__ float sw[FIN * HH];     // 8KB
    __shared__ float sb[HH];
    __shared__ float sx[256 * 33];     // padded: bank-conflict-free scalar reads
    int tid = threadIdx.x;
    for (int i = tid; i < FIN * HH; i += 256) sw[i] = w[i];
    if (tid < HH) sb[tid] = b[tid];

    int n = blockIdx.x * 256 + tid;
    if (n < NN) {
        const float4* xp = reinterpret_cast<const float4*>(x + n * FIN);
#pragma unroll
        for (int q = 0; q < FIN / 4; q++) {
            float4 v = xp[q];
            sx[tid * 33 + q*4 + 0] = v.x; sx[tid * 33 + q*4 + 1] = v.y;
            sx[tid * 33 + q*4 + 2] = v.z; sx[tid * 33 + q*4 + 3] = v.w;
        }
    }
    __syncthreads();
    if (n >= NN) return;

#pragma unroll
    for (int cc = 0; cc < 4; cc++) {
        float acc[16];
#pragma unroll
        for (int c = 0; c < 16; c++) acc[c] = sb[cc*16 + c];
        for (int k = 0; k < FIN; k++) {
            float xk = sx[tid * 33 + k];
            const float4* wp = reinterpret_cast<const float4*>(&sw[k*HH + cc*16]);
#pragma unroll
            for (int q = 0; q < 4; q++) {
                float4 wv = wp[q];
                acc[q*4+0] += xk * wv.x; acc[q*4+1] += xk * wv.y;
                acc[q*4+2] += xk * wv.z; acc[q*4+3] += xk * wv.w;
            }
        }
        float4* ho  = reinterpret_cast<float4*>(g_h  + n*HH + cc*16);
        float4* h0o = reinterpret_cast<float4*>(g_h0 + n*HH + cc*16);
#pragma unroll
        for (int q = 0; q < 4; q++) {
            float4 v = make_float4(acc[q*4], acc[q*4+1], acc[q*4+2], acc[q*4+3]);
            ho[q] = v; h0o[q] = v;
        }
    }
}

// ---------------- prologue A: degree count for all 4 edge sets ------------
__global__ void k_deg(const int* __restrict__ d0, const int* __restrict__ d1,
                      const int* __restrict__ d2, const int* __restrict__ d3) {
    int e = blockIdx.x * 256 + threadIdx.x;
    if (e >= EE) return;
    int j = blockIdx.y;
    const int* d = (j == 0) ? d0 : (j == 1) ? d1 : (j == 2) ? d2 : d3;
    atomicAdd(&g_deg4[j * NN + d[e]], 1);
}

// ---------------- prologue B: bucket lists for all 4 edge sets ------------
__global__ void k_fill4() {
    __shared__ int scnt[NBUK], sbase[NBUK], scur[NBUK];
    int t = threadIdx.x;
    int j = blockIdx.y;
    if (t < NBUK) { scnt[t] = 0; scur[t] = 0; }
    __syncthreads();
    int i = blockIdx.x * 256 + t;
    int b = -1;
    if (i < NN) {
        int d = g_deg4[j * NN + i];
        b = d < NBUK - 1 ? d : NBUK - 1;
        atomicAdd(&scnt[b], 1);
    }
    __syncthreads();
    if (t < NBUK && scnt[t] > 0) sbase[t] = atomicAdd(&g_cnt4[j * NBUK + t], scnt[t]);
    __syncthreads();
    if (i < NN) {
        int pos = atomicAdd(&scur[b], 1);
        g_list4[(j * NBUK + b) * NN + sbase[b] + pos] = i;
    }
}

// ---------------- prologue C: compact (bucket,chunk) work lists -----------
__global__ void k_work() {          // grid = 4 blocks (one per edge set)
    int j = blockIdx.x;
    __shared__ int soff[NBUK + 1];
    if (threadIdx.x == 0) {
        int run = 0;
        for (int b = 0; b < NBUK; b++) {
            soff[b] = run;
            run += (g_cnt4[j * NBUK + b] + NPB - 1) / NPB;
        }
        soff[NBUK] = run;
        g_nwork[j] = run;
    }
    __syncthreads();
    for (int b = 0; b < NBUK; b++) {
        int nch = soff[b + 1] - soff[b];
        for (int c = threadIdx.x; c < nch; c += blockDim.x)
            g_work[j * WORKMAX + soff[b] + c] = (b << 16) | c;
    }
}

// ---------------- K2: scatter  hs[dst] += h[src]  (2 edges / thread) ------
__global__ void k_scatter(const int* __restrict__ src, const int* __restrict__ dst) {
    int t = blockIdx.x * 256 + threadIdx.x;
    int e0 = t >> 4;
    if (e0 >= EE / 2) return;
    int c = (t & 15) * 4;
    int e1 = e0 + EE / 2;
    int s0 = src[e0], d0 = dst[e0];
    int s1 = src[e1], d1 = dst[e1];
    float4 v0 = *reinterpret_cast<const float4*>(&g_h[s0 * HH + c]);
    float4 v1 = *reinterpret_cast<const float4*>(&g_h[s1 * HH + c]);
    red_add_v4(&g_hs[d0 * HH + c], v0);
    red_add_v4(&g_hs[d1 * HH + c], v1);
}

// ---------------- K6: bucketed apply, FFMA2 (register-sane tile) ----------
// out = [hs;h] @ [wl;wr] + bl as one K=128 GEMM per bucket chunk.
// 128 nodes/block, 128 threads, thread tile = 4 node-pairs x 8 cols (32 ULL acc).
// smem: sA[128k][128m] (64KB) + sW[128k][64c] (32KB) + sBL[64] -> 98.6KB, 2 CTA/SM
#define APPLY_SMEM ((128*128 + 128*64 + 64) * 4)

__global__ void __launch_bounds__(128, 2)
k_apply(const float* __restrict__ wl_base,
        const float* __restrict__ bl_base,
        const float* __restrict__ wr_base,
        int relu, int j) {
    if ((int)blockIdx.x >= g_nwork[j]) return;
    int item = g_work[j * WORKMAX + blockIdx.x];
    int b = item >> 16;
    int chunk0 = (item & 0xffff) * NPB;
    int cnt = g_cnt4[j * NBUK + b];
    const int* list = g_list4 + (j * NBUK + b) * NN + chunk0;
    int nv = cnt - chunk0; if (nv > NPB) nv = NPB;
    int tid = threadIdx.x;

    if (b == 0) {                       // deg==0: h unchanged, relu still applies
        if (!relu) return;
        for (int idx = tid; idx < nv * 16; idx += 128) {
            int n = list[idx >> 4];
            int c = (idx & 15) * 4;
            float4* p = reinterpret_cast<float4*>(&g_h[n * HH + c]);
            float4 v = *p;
            v.x = fmaxf(v.x, 0.f); v.y = fmaxf(v.y, 0.f);
            v.z = fmaxf(v.z, 0.f); v.w = fmaxf(v.w, 0.f);
            *p = v;
        }
        return;
    }

    extern __shared__ float sm[];
    float* sA  = sm;                 // [k=0..127][m=0..127]; k<64: hs, k>=64: h
    float* sW  = sm + 128 * 128;     // [k=0..127][c=0..63];  k<64: wl, k>=64: wr
    float* sBL = sm + 128 * 128 + 128 * 64;

    const float* wl = wl_base + b * HH * HH;
    const float* wr = wr_base + b * HH * HH;
    const float* bl = bl_base + b * HH;

    // stage weights (un-duplicated): 1024 float4 per matrix
    for (int i = tid; i < 1024; i += 128) {
        reinterpret_cast<float4*>(sW)[i]        = reinterpret_cast<const float4*>(wl)[i];
        reinterpret_cast<float4*>(sW)[i + 1024] = reinterpret_cast<const float4*>(wr)[i];
    }
    if (tid < HH) sBL[tid] = bl[tid];

    // stage activations transposed: thread m stages node list[m]
    {
        int m = tid;
        int node = (m < nv) ? list[m] : -1;
        const float4* ha = (node >= 0) ? reinterpret_cast<const float4*>(&g_hs[node * HH]) : nullptr;
        const float4* hb = (node >= 0) ? reinterpret_cast<const float4*>(&g_h [node * HH]) : nullptr;
#pragma unroll
        for (int q = 0; q < 16; q++) {
            float4 va = (node >= 0) ? ha[q] : make_float4(0.f,0.f,0.f,0.f);
            float4 vb = (node >= 0) ? hb[q] : make_float4(0.f,0.f,0.f,0.f);
            int k0 = q * 4;
            sA[(k0+0)*128 + m] = va.x; sA[(k0+1)*128 + m] = va.y;
            sA[(k0+2)*128 + m] = va.z; sA[(k0+3)*128 + m] = va.w;
            sA[(64+k0+0)*128 + m] = vb.x; sA[(64+k0+1)*128 + m] = vb.y;
            sA[(64+k0+2)*128 + m] = vb.z; sA[(64+k0+3)*128 + m] = vb.w;
        }
    }
    __syncthreads();

    int tx = tid & 7;          // col group: cols tx*8 .. tx*8+7
    int ty = tid >> 3;         // pair group: nodes ty*8 .. ty*8+7 (4 pairs)
    int m0 = ty * 8;

    unsigned long long acc[4][8];
#pragma unroll
    for (int c = 0; c < 8; c++) {
        unsigned long long pb = dup2(sBL[tx*8 + c]);
#pragma unroll
        for (int p = 0; p < 4; p++) acc[p][c] = pb;
    }

#pragma unroll 4
    for (int k = 0; k < 128; k++) {
        const U2* ap = reinterpret_cast<const U2*>(sA + k * 128 + m0);
        U2 aA = ap[0], aB = ap[1];               // 4 node-pairs
        const float4* wp = reinterpret_cast<const float4*>(sW + k * 64 + tx * 8);
        float4 w0 = wp[0], w1 = wp[1];
        unsigned long long wd[8];
        wd[0] = dup2(w0.x); wd[1] = dup2(w0.y); wd[2] = dup2(w0.z); wd[3] = dup2(w0.w);
        wd[4] = dup2(w1.x); wd[5] = dup2(w1.y); wd[6] = dup2(w1.z); wd[7] = dup2(w1.w);
        unsigned long long av[4] = {aA.x, aA.y, aB.x, aB.y};
#pragma unroll
        for (int p = 0; p < 4; p++) {
            unsigned long long a = av[p];
#pragma unroll
            for (int c = 0; c < 8; c++)
                acc[p][c] = ffma2(a, wd[c], acc[p][c]);
        }
    }

    // epilogue: pair p holds nodes (m0+2p, m0+2p+1) in (lo, hi) lanes
#pragma unroll
    for (int p = 0; p < 4; p++) {
        int m = m0 + 2 * p;
#pragma unroll
        for (int half = 0; half < 2; half++) {
            if (m + half < nv) {
                int node = list[m + half];
                float f[8];
#pragma unroll
                for (int c = 0; c < 8; c++)
                    f[c] = half ? hi32(acc[p][c]) : lo32(acc[p][c]);
                if (relu) {
#pragma unroll
                    for (int c = 0; c < 8; c++) f[c] = fmaxf(f[c], 0.f);
                }
                float4* o = reinterpret_cast<float4*>(&g_h[node * HH + tx * 8]);
                o[0] = make_float4(f[0], f[1], f[2], f[3]);
                o[1] = make_float4(f[4], f[5], f[6], f[7]);
            }
        }
    }
}

// ---------------- K7: LayerNorm + residual --------------------------------
__global__ void k_ln(const float* __restrict__ g, const float* __restrict__ bb) {
    int wid = (blockIdx.x * 256 + threadIdx.x) >> 5;
    int lane = threadIdx.x & 31;
    if (wid >= NN) return;
    const float* hp = g_h + wid * HH;
    float v0 = hp[lane], v1 = hp[lane + 32];
    float s = v0 + v1;
#pragma unroll
    for (int o = 16; o > 0; o >>= 1) s += __shfl_xor_sync(0xffffffffu, s, o);
    float mu = s * (1.f / 64.f);
    float d0 = v0 - mu, d1 = v1 - mu;
    float q = d0 * d0 + d1 * d1;
#pragma unroll
    for (int o = 16; o > 0; o >>= 1) q += __shfl_xor_sync(0xffffffffu, q, o);
    float rstd = rsqrtf(q * (1.f / 64.f) + LN_EPS);
    const float* h0p = g_h0 + wid * HH;
    g_h[wid*HH + lane]      = d0 * rstd * g[lane]      + bb[lane]      + h0p[lane];
    g_h[wid*HH + lane + 32] = d1 * rstd * g[lane + 32] + bb[lane + 32] + h0p[lane + 32];
}

// ---------------- K8: pooled[batch[i]] += h[i] for ground nodes (i<G) -----
__global__ void k_pool(const int* __restrict__ batch_idx) {
    int t = blockIdx.x * 256 + threadIdx.x;
    int i = t >> 4;
    if (i >= GG) return;
    int c = (t & 15) * 4;
    int gidx = batch_idx[i];
    float4 v = *reinterpret_cast<const float4*>(&g_h[i * HH + c]);
    red_add_v4(&g_pooled[gidx * HH + c], v);
}

// ---------------- K9: out = pooled @ out_w + out_b ------------------------
__global__ void k_out(const float* __restrict__ ow, const float* __restrict__ ob,
                      float* __restrict__ out) {
    int gidx = threadIdx.x;           // 128 threads
    float acc = ob[0];
#pragma unroll
    for (int k = 0; k < HH; k++) acc += g_pooled[gidx * HH + k] * ow[k];
    out[gidx] = acc;
}

// ---------------- host launcher ------------------------------------------
extern "C" void kernel_launch(void* const* d_in, const int* in_sizes, int n_in,
                              void* d_out, int out_size) {
    (void)in_sizes; (void)n_in; (void)out_size;
    const float* x        = (const float*)d_in[0];
    // reference edge-set order: edge_index, node_subnode, subgraph_edge, subnode_node
    const int* eis[4] = { (const int*)d_in[1], (const int*)d_in[3],
                          (const int*)d_in[2], (const int*)d_in[4] };
    const int*   batch_idx = (const int*)d_in[7];
    const float* emb_w  = (const float*)d_in[8];
    const float* emb_b  = (const float*)d_in[9];
    const float* conv_wl = (const float*)d_in[10];
    const float* conv_bl = (const float*)d_in[11];
    const float* conv_wr = (const float*)d_in[12];
    const float* ln_g   = (const float*)d_in[13];
    const float* ln_b   = (const float*)d_in[14];
    const float* out_w  = (const float*)d_in[15];
    const float* out_b  = (const float*)d_in[16];
    float* out = (float*)d_out;

    void *p_hs, *p_deg4, *p_cnt4, *p_pooled;
    cudaGetSymbolAddress(&p_hs, g_hs);
    cudaGetSymbolAddress(&p_deg4, g_deg4);
    cudaGetSymbolAddress(&p_cnt4, g_cnt4);
    cudaGetSymbolAddress(&p_pooled, g_pooled);

    cudaFuncSetAttribute(k_apply, cudaFuncAttributeMaxDynamicSharedMemorySize,
                         APPLY_SMEM);

    // ---- prologue: structure-only bucketing + work lists (all 4 edge sets)
    cudaMemsetAsync(p_deg4, 0, sizeof(int) * 4 * NN);
    cudaMemsetAsync(p_cnt4, 0, sizeof(int) * 4 * NBUK);
    {
        dim3 gd((EE + 255) / 256, 4);
        k_deg<<<gd, 256>>>(eis[0] + EE, eis[1] + EE, eis[2] + EE, eis[3] + EE);
        dim3 gf((NN + 255) / 256, 4);
        k_fill4<<<gf, 256>>>();
        k_work<<<4, 256>>>();
    }

    k_embed<<<(NN + 255) / 256, 256>>>(x, emb_w, emb_b);

    for (int j = 0; j < 4; j++) {
        cudaMemsetAsync(p_hs, 0, sizeof(float) * NN * HH);
        k_scatter<<<(EE * 8 + 255) / 256, 256>>>(eis[j], eis[j] + EE);
        k_apply<<<WORKMAX, 128, APPLY_SMEM>>>(conv_wl + j * NBUK * HH * HH,
                                              conv_bl + j * NBUK * HH,
                                              conv_wr + j * NBUK * HH * HH,
                                              (j < 3) ? 1 : 0, j);
    }

    k_ln<<<(NN * 32 + 255) / 256, 256>>>(ln_g, ln_b);

    cudaMemsetAsync(p_pooled, 0, sizeof(float) * NGRAPH * HH);
    k_pool<<<(GG * 16 + 255) / 256, 256>>>(batch_idx);
    k_out<<<1, NGRAPH>>>(out_w, out_b, out);
}

// round 11
// speedup vs baseline: 1.5319x; 1.0636x over previous
#include <cuda_runtime.h>
#include <cuda_bf16.h>

// ---------------- problem constants (fixed by the dataset) ----------------
#define NN      100000      // total nodes
#define HH      64          // hidden features
#define EE      800000      // edges per edge set
#define GG      50000       // ground nodes (ground_node = arange(N) < G)
#define NGRAPH  128
#define FIN     32
#define NBUK    21          // degree buckets 0..20 (bucket 0 <=> deg==0 <=> passthrough)
#define NPB     128         // nodes per apply-GEMM block
#define LN_EPS  1e-5f
#define SCB     98          // scan blocks per edge set = ceil(NN/1024)

// ---------------- scratch (static device globals; no allocation) ----------
__device__ float g_h  [NN * HH];
__device__ float g_h0 [NN * HH];
__device__ float g_hs [NN * HH];
__device__ int   g_deg4 [4 * NN];
__device__ int   g_cnt4 [4 * NBUK];
__device__ int   g_list4[4 * NBUK * NN];
__device__ int   g_iscan[4 * NN];
__device__ int   g_bsum [4 * SCB];
__device__ int   g_boff [4 * SCB];
__device__ int   g_rowptr4[4 * (NN + 1)];
__device__ int   g_cur4 [4 * NN];
__device__ int   g_ssrc4[4 * EE];        // edges sorted by dst (src ids)
__device__ float g_pooled[NGRAPH * HH];

// vector f32 reduction (PTX ISA 8.1+, sm_90+): 1 L2 atomic op for 16B
__device__ __forceinline__ void red_add_v4(float* p, float4 v) {
    asm volatile("red.global.add.v4.f32 [%0], {%1, %2, %3, %4};"
                 :: "l"(p), "f"(v.x), "f"(v.y), "f"(v.z), "f"(v.w) : "memory");
}

// packed fp32x2 FMA (Blackwell; only reachable via PTX)
__device__ __forceinline__ unsigned long long ffma2(unsigned long long a,
                                                    unsigned long long b,
                                                    unsigned long long c) {
    unsigned long long d;
    asm("fma.rn.f32x2 %0, %1, %2, %3;" : "=l"(d) : "l"(a), "l"(b), "l"(c));
    return d;
}
__device__ __forceinline__ unsigned long long dup2(float v) {
    unsigned u = __float_as_uint(v);
    unsigned long long r;
    asm("mov.b64 %0, {%1, %1};" : "=l"(r) : "r"(u));
    return r;
}
__device__ __forceinline__ float lo32(unsigned long long v) {
    return __uint_as_float((unsigned)v);
}
__device__ __forceinline__ float hi32(unsigned long long v) {
    return __uint_as_float((unsigned)(v >> 32));
}
struct __align__(16) U2 { unsigned long long x, y; };

// ---------------- K0: zero all accumulators in one launch -----------------
__global__ void k_zero() {
    int i = blockIdx.x * 256 + threadIdx.x;
    if (i < 4 * NN) g_deg4[i] = 0;
    if (i < 4 * NBUK) g_cnt4[i] = 0;
    if (i < NGRAPH * HH) g_pooled[i] = 0.f;
}

// ---------------- K1: embedding  h = x @ emb_w + emb_b ; h0 = h ----------
__global__ void k_embed(const float* __restrict__ x,
                        const float* __restrict__ w,
                        const float* __restrict__ b) {
    __shared__ float sw[FIN * HH];
    __shared__ float sb[HH];
    for (int i = threadIdx.x; i < FIN * HH; i += 256) sw[i] = w[i];
    if (threadIdx.x < HH) sb[threadIdx.x] = b[threadIdx.x];
    __syncthreads();

    int n = blockIdx.x * 256 + threadIdx.x;
    if (n >= NN) return;

    float xv[FIN];
    const float4* xp = reinterpret_cast<const float4*>(x + n * FIN);
#pragma unroll
    for (int q = 0; q < FIN / 4; q++) {
        float4 v = xp[q];
        xv[q*4+0] = v.x; xv[q*4+1] = v.y; xv[q*4+2] = v.z; xv[q*4+3] = v.w;
    }

#pragma unroll
    for (int cc = 0; cc < 4; cc++) {
        float acc[16];
#pragma unroll
        for (int c = 0; c < 16; c++) acc[c] = sb[cc*16 + c];
#pragma unroll
        for (int k = 0; k < FIN; k++) {
            float xk = xv[k];
#pragma unroll
            for (int c = 0; c < 16; c++) acc[c] += xk * sw[k*HH + cc*16 + c];
        }
        float4* ho  = reinterpret_cast<float4*>(g_h  + n*HH + cc*16);
        float4* h0o = reinterpret_cast<float4*>(g_h0 + n*HH + cc*16);
#pragma unroll
        for (int q = 0; q < 4; q++) {
            float4 v = make_float4(acc[q*4], acc[q*4+1], acc[q*4+2], acc[q*4+3]);
            ho[q] = v; h0o[q] = v;
        }
    }
}

// ---------------- prologue A: degree count for all 4 edge sets ------------
__global__ void k_deg(const int* __restrict__ d0, const int* __restrict__ d1,
                      const int* __restrict__ d2, const int* __restrict__ d3) {
    int e = blockIdx.x * 256 + threadIdx.x;
    if (e >= EE) return;
    int j = blockIdx.y;
    const int* d = (j == 0) ? d0 : (j == 1) ? d1 : (j == 2) ? d2 : d3;
    atomicAdd(&g_deg4[j * NN + d[e]], 1);
}

// ---------------- prologue: 2-level exclusive scan of deg -> rowptr -------
__global__ void k_scanA() {              // grid (SCB, 4), 1024 threads
    __shared__ int tmp[1024];
    int j = blockIdx.y;
    int gid = blockIdx.x * 1024 + threadIdx.x;
    int v = (gid < NN) ? g_deg4[j * NN + gid] : 0;
    tmp[threadIdx.x] = v; __syncthreads();
    for (int off = 1; off < 1024; off <<= 1) {
        int x = (threadIdx.x >= off) ? tmp[threadIdx.x - off] : 0;
        __syncthreads();
        tmp[threadIdx.x] += x;
        __syncthreads();
    }
    if (gid < NN) g_iscan[j * NN + gid] = tmp[threadIdx.x];
    if (threadIdx.x == 1023) g_bsum[j * SCB + blockIdx.x] = tmp[1023];
}

__global__ void k_scanB() {              // grid (4), 128 threads
    __shared__ int tmp[128];
    int j = blockIdx.x;
    int v = (threadIdx.x < SCB) ? g_bsum[j * SCB + threadIdx.x] : 0;
    tmp[threadIdx.x] = v; __syncthreads();
    for (int off = 1; off < 128; off <<= 1) {
        int x = (threadIdx.x >= off) ? tmp[threadIdx.x - off] : 0;
        __syncthreads();
        tmp[threadIdx.x] += x;
        __syncthreads();
    }
    if (threadIdx.x < SCB) g_boff[j * SCB + threadIdx.x] = tmp[threadIdx.x] - v;
}

__global__ void k_scanC() {              // grid (SCB, 4), 1024 threads
    int j = blockIdx.y;
    int gid = blockIdx.x * 1024 + threadIdx.x;
    if (gid < NN) {
        int ex = g_iscan[j * NN + gid] - g_deg4[j * NN + gid]
               + g_boff[j * SCB + blockIdx.x];
        g_rowptr4[j * (NN + 1) + gid] = ex;
        g_cur4[j * NN + gid] = ex;
        if (gid == NN - 1) g_rowptr4[j * (NN + 1) + NN] = EE;
    }
}

// ---------------- prologue: bin edges by dst (CSR) ------------------------
__global__ void k_binE(const int* __restrict__ s0, const int* __restrict__ s1,
                       const int* __restrict__ s2, const int* __restrict__ s3) {
    int e = blockIdx.x * 256 + threadIdx.x;
    if (e >= EE) return;
    int j = blockIdx.y;
    const int* sp = (j == 0) ? s0 : (j == 1) ? s1 : (j == 2) ? s2 : s3;
    int d = sp[EE + e];                  // dst row of the (2,E) tensor
    int s = sp[e];                       // src row
    int pos = atomicAdd(&g_cur4[j * NN + d], 1);
    g_ssrc4[j * EE + pos] = s;
}

// ---------------- prologue B: bucket lists for all 4 edge sets ------------
__global__ void k_fill4() {
    __shared__ int scnt[NBUK], sbase[NBUK], scur[NBUK];
    int t = threadIdx.x;
    int j = blockIdx.y;
    if (t < NBUK) { scnt[t] = 0; scur[t] = 0; }
    __syncthreads();
    int i = blockIdx.x * 256 + t;
    int b = -1;
    if (i < NN) {
        int d = g_deg4[j * NN + i];
        b = d < NBUK - 1 ? d : NBUK - 1;
        atomicAdd(&scnt[b], 1);
    }
    __syncthreads();
    if (t < NBUK && scnt[t] > 0) sbase[t] = atomicAdd(&g_cnt4[j * NBUK + t], scnt[t]);
    __syncthreads();
    if (i < NN) {
        int pos = atomicAdd(&scur[b], 1);
        g_list4[(j * NBUK + b) * NN + sbase[b] + pos] = i;
    }
}

// ---------------- K2: gather segment-sum  hs[d] = sum_{e in seg(d)} h[src] -
// one warp per dst; contiguous sorted edge segment; no atomics, no memset.
__global__ void k_gather(int j) {
    int d = (blockIdx.x * 256 + threadIdx.x) >> 5;
    if (d >= NN) return;
    int lane = threadIdx.x & 31;
    const int* rp = g_rowptr4 + j * (NN + 1);
    int beg = rp[d], end = rp[d + 1];
    if (beg == end) return;              // deg==0: hs never read (bucket 0)
    const int* ss = g_ssrc4 + j * EE;
    float2 acc = make_float2(0.f, 0.f);
    int e = beg;
    for (; e + 4 <= end; e += 4) {
        int s0 = ss[e], s1 = ss[e+1], s2 = ss[e+2], s3 = ss[e+3];
        float2 v0 = *reinterpret_cast<const float2*>(&g_h[s0 * HH + lane * 2]);
        float2 v1 = *reinterpret_cast<const float2*>(&g_h[s1 * HH + lane * 2]);
        float2 v2 = *reinterpret_cast<const float2*>(&g_h[s2 * HH + lane * 2]);
        float2 v3 = *reinterpret_cast<const float2*>(&g_h[s3 * HH + lane * 2]);
        acc.x += (v0.x + v1.x) + (v2.x + v3.x);
        acc.y += (v0.y + v1.y) + (v2.y + v3.y);
    }
    for (; e < end; e++) {
        int s = ss[e];
        float2 v = *reinterpret_cast<const float2*>(&g_h[s * HH + lane * 2]);
        acc.x += v.x; acc.y += v.y;
    }
    *reinterpret_cast<float2*>(&g_hs[d * HH + lane * 2]) = acc;
}

// ---------------- K6: bucketed apply, FFMA2 -------------------------------
// out = [hs;h] @ [wl;wr] + bl as one K=128 GEMM per bucket chunk.
// 128 nodes/block, 128 threads, thread tile = 4 node-pairs x 8 cols.
// smem: sA[128k][128m] (64KB) + sW[128k][64c] (32KB) + sBL[64] -> 2 CTA/SM
#define APPLY_SMEM ((128*128 + 128*64 + 64) * 4)
#define AGRID 832

__global__ void __launch_bounds__(128, 2)
k_apply(const float* __restrict__ wl_base,
        const float* __restrict__ bl_base,
        const float* __restrict__ wr_base,
        int relu, int j) {
    // derive (bucket, chunk) from blockIdx by walking the 21 bucket counts
    int b = -1, chunk0 = 0, cnt = 0;
    {
        int rem = blockIdx.x;
        for (int bb = 0; bb < NBUK; bb++) {
            int c = g_cnt4[j * NBUK + bb];
            int nch = (c + NPB - 1) >> 7;
            if (rem < nch) { b = bb; chunk0 = rem * NPB; cnt = c; break; }
            rem -= nch;
        }
    }
    if (b < 0) return;
    const int* list = g_list4 + (j * NBUK + b) * NN + chunk0;
    int nv = cnt - chunk0; if (nv > NPB) nv = NPB;
    int tid = threadIdx.x;

    if (b == 0) {                       // deg==0: h unchanged, relu still applies
        if (!relu) return;
        for (int idx = tid; idx < nv * 16; idx += 128) {
            int n = list[idx >> 4];
            int c = (idx & 15) * 4;
            float4* p = reinterpret_cast<float4*>(&g_h[n * HH + c]);
            float4 v = *p;
            v.x = fmaxf(v.x, 0.f); v.y = fmaxf(v.y, 0.f);
            v.z = fmaxf(v.z, 0.f); v.w = fmaxf(v.w, 0.f);
            *p = v;
        }
        return;
    }

    extern __shared__ float sm[];
    float* sA  = sm;                 // [k=0..127][m=0..127]; k<64: hs, k>=64: h
    float* sW  = sm + 128 * 128;     // [k=0..127][c=0..63];  k<64: wl, k>=64: wr
    float* sBL = sm + 128 * 128 + 128 * 64;

    const float* wl = wl_base + b * HH * HH;
    const float* wr = wr_base + b * HH * HH;
    const float* bl = bl_base + b * HH;

    for (int i = tid; i < 1024; i += 128) {
        reinterpret_cast<float4*>(sW)[i]        = reinterpret_cast<const float4*>(wl)[i];
        reinterpret_cast<float4*>(sW)[i + 1024] = reinterpret_cast<const float4*>(wr)[i];
    }
    if (tid < HH) sBL[tid] = bl[tid];

    {
        int m = tid;
        int node = (m < nv) ? list[m] : -1;
        const float4* ha = (node >= 0) ? reinterpret_cast<const float4*>(&g_hs[node * HH]) : nullptr;
        const float4* hb = (node >= 0) ? reinterpret_cast<const float4*>(&g_h [node * HH]) : nullptr;
#pragma unroll
        for (int q = 0; q < 16; q++) {
            float4 va = (node >= 0) ? ha[q] : make_float4(0.f,0.f,0.f,0.f);
            float4 vb = (node >= 0) ? hb[q] : make_float4(0.f,0.f,0.f,0.f);
            int k0 = q * 4;
            sA[(k0+0)*128 + m] = va.x; sA[(k0+1)*128 + m] = va.y;
            sA[(k0+2)*128 + m] = va.z; sA[(k0+3)*128 + m] = va.w;
            sA[(64+k0+0)*128 + m] = vb.x; sA[(64+k0+1)*128 + m] = vb.y;
            sA[(64+k0+2)*128 + m] = vb.z; sA[(64+k0+3)*128 + m] = vb.w;
        }
    }
    __syncthreads();

    int tx = tid & 7;          // col group: cols tx*8 .. tx*8+7
    int ty = tid >> 3;         // pair group: nodes ty*8 .. ty*8+7 (4 pairs)
    int m0 = ty * 8;

    unsigned long long acc[4][8];
#pragma unroll
    for (int c = 0; c < 8; c++) {
        unsigned long long pb = dup2(sBL[tx*8 + c]);
#pragma unroll
        for (int p = 0; p < 4; p++) acc[p][c] = pb;
    }

#pragma unroll 4
    for (int k = 0; k < 128; k++) {
        const U2* ap = reinterpret_cast<const U2*>(sA + k * 128 + m0);
        U2 aA = ap[0], aB = ap[1];
        const float4* wp = reinterpret_cast<const float4*>(sW + k * 64 + tx * 8);
        float4 w0 = wp[0], w1 = wp[1];
        unsigned long long wd[8];
        wd[0] = dup2(w0.x); wd[1] = dup2(w0.y); wd[2] = dup2(w0.z); wd[3] = dup2(w0.w);
        wd[4] = dup2(w1.x); wd[5] = dup2(w1.y); wd[6] = dup2(w1.z); wd[7] = dup2(w1.w);
        unsigned long long av[4] = {aA.x, aA.y, aB.x, aB.y};
#pragma unroll
        for (int p = 0; p < 4; p++) {
            unsigned long long a = av[p];
#pragma unroll
            for (int c = 0; c < 8; c++)
                acc[p][c] = ffma2(a, wd[c], acc[p][c]);
        }
    }

#pragma unroll
    for (int p = 0; p < 4; p++) {
        int m = m0 + 2 * p;
#pragma unroll
        for (int half = 0; half < 2; half++) {
            if (m + half < nv) {
                int node = list[m + half];
                float f[8];
#pragma unroll
                for (int c = 0; c < 8; c++)
                    f[c] = half ? hi32(acc[p][c]) : lo32(acc[p][c]);
                if (relu) {
#pragma unroll
                    for (int c = 0; c < 8; c++) f[c] = fmaxf(f[c], 0.f);
                }
                float4* o = reinterpret_cast<float4*>(&g_h[node * HH + tx * 8]);
                o[0] = make_float4(f[0], f[1], f[2], f[3]);
                o[1] = make_float4(f[4], f[5], f[6], f[7]);
            }
        }
    }
}

// ---------------- K7: LayerNorm + residual --------------------------------
__global__ void k_ln(const float* __restrict__ g, const float* __restrict__ bb) {
    int wid = (blockIdx.x * 256 + threadIdx.x) >> 5;
    int lane = threadIdx.x & 31;
    if (wid >= NN) return;
    const float* hp = g_h + wid * HH;
    float v0 = hp[lane], v1 = hp[lane + 32];
    float s = v0 + v1;
#pragma unroll
    for (int o = 16; o > 0; o >>= 1) s += __shfl_xor_sync(0xffffffffu, s, o);
    float mu = s * (1.f / 64.f);
    float d0 = v0 - mu, d1 = v1 - mu;
    float q = d0 * d0 + d1 * d1;
#pragma unroll
    for (int o = 16; o > 0; o >>= 1) q += __shfl_xor_sync(0xffffffffu, q, o);
    float rstd = rsqrtf(q * (1.f / 64.f) + LN_EPS);
    const float* h0p = g_h0 + wid * HH;
    g_h[wid*HH + lane]      = d0 * rstd * g[lane]      + bb[lane]      + h0p[lane];
    g_h[wid*HH + lane + 32] = d1 * rstd * g[lane + 32] + bb[lane + 32] + h0p[lane + 32];
}

// ---------------- K8: pooled[batch[i]] += h[i] for ground nodes (i<G) -----
__global__ void k_pool(const int* __restrict__ batch_idx) {
    int t = blockIdx.x * 256 + threadIdx.x;
    int i = t >> 4;
    if (i >= GG) return;
    int c = (t & 15) * 4;
    int gidx = batch_idx[i];
    float4 v = *reinterpret_cast<const float4*>(&g_h[i * HH + c]);
    red_add_v4(&g_pooled[gidx * HH + c], v);
}

// ---------------- K9: out = pooled @ out_w + out_b ------------------------
__global__ void k_out(const float* __restrict__ ow, const float* __restrict__ ob,
                      float* __restrict__ out) {
    int gidx = threadIdx.x;           // 128 threads
    float acc = ob[0];
#pragma unroll
    for (int k = 0; k < HH; k++) acc += g_pooled[gidx * HH + k] * ow[k];
    out[gidx] = acc;
}

// ---------------- host launcher ------------------------------------------
extern "C" void kernel_launch(void* const* d_in, const int* in_sizes, int n_in,
                              void* d_out, int out_size) {
    (void)in_sizes; (void)n_in; (void)out_size;
    const float* x        = (const float*)d_in[0];
    // reference edge-set order: edge_index, node_subnode, subgraph_edge, subnode_node
    const int* eis[4] = { (const int*)d_in[1], (const int*)d_in[3],
                          (const int*)d_in[2], (const int*)d_in[4] };
    const int*   batch_idx = (const int*)d_in[7];
    const float* emb_w  = (const float*)d_in[8];
    const float* emb_b  = (const float*)d_in[9];
    const float* conv_wl = (const float*)d_in[10];
    const float* conv_bl = (const float*)d_in[11];
    const float* conv_wr = (const float*)d_in[12];
    const float* ln_g   = (const float*)d_in[13];
    const float* ln_b   = (const float*)d_in[14];
    const float* out_w  = (const float*)d_in[15];
    const float* out_b  = (const float*)d_in[16];
    float* out = (float*)d_out;

    cudaFuncSetAttribute(k_apply, cudaFuncAttributeMaxDynamicSharedMemorySize,
                         APPLY_SMEM);

    // ---- prologue: structure-only CSR + bucketing (all 4 edge sets) ----
    k_zero<<<(4 * NN + 255) / 256, 256>>>();
    {
        dim3 gd((EE + 255) / 256, 4);
        k_deg<<<gd, 256>>>(eis[0] + EE, eis[1] + EE, eis[2] + EE, eis[3] + EE);
        dim3 gs(SCB, 4);
        k_scanA<<<gs, 1024>>>();
        k_scanB<<<4, 128>>>();
        k_scanC<<<gs, 1024>>>();
        k_binE<<<gd, 256>>>(eis[0], eis[1], eis[2], eis[3]);   // capture slot 6
        dim3 gf((NN + 255) / 256, 4);
        k_fill4<<<gf, 256>>>();
    }

    k_embed<<<(NN + 255) / 256, 256>>>(x, emb_w, emb_b);

    for (int j = 0; j < 4; j++) {
        k_gather<<<(NN * 32 + 255) / 256, 256>>>(j);
        k_apply<<<AGRID, 128, APPLY_SMEM>>>(conv_wl + j * NBUK * HH * HH,
                                            conv_bl + j * NBUK * HH,
                                            conv_wr + j * NBUK * HH * HH,
                                            (j < 3) ? 1 : 0, j);
    }

    k_ln<<<(NN * 32 + 255) / 256, 256>>>(ln_g, ln_b);
    k_pool<<<(GG * 16 + 255) / 256, 256>>>(batch_idx);
    k_out<<<1, NGRAPH>>>(out_w, out_b, out);
}

// round 16
// speedup vs baseline: 1.7651x; 1.1523x over previous
#include <cuda_runtime.h>
#include <cuda_bf16.h>

// ---------------- problem constants (fixed by the dataset) ----------------
#define NN      100000      // total nodes
#define HH      64          // hidden features
#define EE      800000      // edges per edge set
#define GG      50000       // ground nodes (ground_node = arange(N) < G)
#define NGRAPH  128
#define FIN     32
#define NBUK    21          // degree buckets 0..20 (bucket 0 <=> deg==0 <=> passthrough)
#define NPB     128         // nodes per apply-GEMM block
#define LN_EPS  1e-5f
#define SCB     98          // scan blocks per edge set = ceil(NN/1024)

// ---------------- scratch (static device globals; no allocation) ----------
__device__ float g_h  [NN * HH];
__device__ float g_h0 [NN * HH];
__device__ float g_hs [NN * HH];
__device__ int   g_deg4 [4 * NN];
__device__ int   g_cnt4 [4 * NBUK];
__device__ int   g_list4[4 * NBUK * NN];
__device__ int   g_iscan[4 * NN];
__device__ int   g_bsum [4 * SCB];
__device__ int   g_boff [4 * SCB];
__device__ int   g_rowptr4[4 * (NN + 1)];
__device__ int   g_cur4 [4 * NN];
__device__ int   g_ssrc4[4 * EE];        // edges sorted by dst (src ids)
__device__ float g_pooled[NGRAPH * HH];

// vector f32 reduction (PTX ISA 8.1+, sm_90+): 1 L2 atomic op for 16B
__device__ __forceinline__ void red_add_v4(float* p, float4 v) {
    asm volatile("red.global.add.v4.f32 [%0], {%1, %2, %3, %4};"
                 :: "l"(p), "f"(v.x), "f"(v.y), "f"(v.z), "f"(v.w) : "memory");
}

// fp32 -> tf32 (round-to-nearest) ; result kept in a 32-bit container
__device__ __forceinline__ float cvt_tf32(float x) {
    unsigned r;
    asm("cvt.rna.tf32.f32 %0, %1;" : "=r"(r) : "f"(x));
    return __uint_as_float(r);
}
__device__ __forceinline__ float4 cvt_tf32_v4(float4 v) {
    return make_float4(cvt_tf32(v.x), cvt_tf32(v.y), cvt_tf32(v.z), cvt_tf32(v.w));
}

// m16n8k8 tf32 MMA, D = A*B + D (C aliased to D)
__device__ __forceinline__ void mma_tf32(float* c,
                                         unsigned a0, unsigned a1,
                                         unsigned a2, unsigned a3,
                                         unsigned b0, unsigned b1) {
    asm volatile("mma.sync.aligned.m16n8k8.row.col.f32.tf32.tf32.f32 "
                 "{%0,%1,%2,%3}, {%4,%5,%6,%7}, {%8,%9}, {%0,%1,%2,%3};"
                 : "+f"(c[0]), "+f"(c[1]), "+f"(c[2]), "+f"(c[3])
                 : "r"(a0), "r"(a1), "r"(a2), "r"(a3), "r"(b0), "r"(b1));
}

// ---------------- K0: zero all accumulators in one launch -----------------
__global__ void k_zero() {
    int i = blockIdx.x * 256 + threadIdx.x;
    if (i < 4 * NN) g_deg4[i] = 0;
    if (i < 4 * NBUK) g_cnt4[i] = 0;
    if (i < NGRAPH * HH) g_pooled[i] = 0.f;
}

// ---------------- K1: embedding via tf32 MMA ------------------------------
// h = x @ emb_w + emb_b ; h0 = h.  Per block: M=128 nodes, K=32, N=64.
#define EPAD 36   // K=32 + pad 4
__global__ void __launch_bounds__(128, 2)
k_embed(const float* __restrict__ x,
        const float* __restrict__ w,
        const float* __restrict__ bias) {
    __shared__ float sX[128 * EPAD];      // [m][k]
    __shared__ float sWT[HH * EPAD];      // [n][k]
    __shared__ float sb[HH];
    int tid = threadIdx.x;
    int base = blockIdx.x * 128;

    for (int i = tid; i < FIN * HH; i += 128) {
        int k = i >> 6, n = i & 63;
        sWT[n * EPAD + k] = cvt_tf32(w[i]);          // w[k][n]
    }
    if (tid < HH) sb[tid] = bias[tid];
    {
        int node = base + tid;
        float* row = sX + tid * EPAD;
        if (node < NN) {
            const float4* xp = reinterpret_cast<const float4*>(x + node * FIN);
#pragma unroll
            for (int q = 0; q < FIN / 4; q++)
                *reinterpret_cast<float4*>(row + q * 4) = cvt_tf32_v4(xp[q]);
        } else {
#pragma unroll
            for (int q = 0; q < FIN / 4; q++)
                *reinterpret_cast<float4*>(row + q * 4) = make_float4(0,0,0,0);
        }
    }
    __syncthreads();

    int lane = tid & 31, wid = tid >> 5;
    int g = lane >> 2, t = lane & 3;

    float acc[2][8][4];
#pragma unroll
    for (int am = 0; am < 2; am++)
#pragma unroll
        for (int an = 0; an < 8; an++) {
            float b0 = sb[an * 8 + 2 * t], b1 = sb[an * 8 + 2 * t + 1];
            acc[am][an][0] = b0; acc[am][an][1] = b1;
            acc[am][an][2] = b0; acc[am][an][3] = b1;
        }

    const unsigned* uX = reinterpret_cast<const unsigned*>(sX);
    const unsigned* uW = reinterpret_cast<const unsigned*>(sWT);
#pragma unroll
    for (int ks = 0; ks < FIN / 8; ks++) {
        int k0 = ks * 8;
        unsigned a[2][4];
#pragma unroll
        for (int am = 0; am < 2; am++) {
            int mr = wid * 32 + am * 16 + g;
            a[am][0] = uX[mr * EPAD + k0 + t];
            a[am][1] = uX[(mr + 8) * EPAD + k0 + t];
            a[am][2] = uX[mr * EPAD + k0 + t + 4];
            a[am][3] = uX[(mr + 8) * EPAD + k0 + t + 4];
        }
#pragma unroll
        for (int an = 0; an < 8; an++) {
            unsigned b0 = uW[(an * 8 + g) * EPAD + k0 + t];
            unsigned b1 = uW[(an * 8 + g) * EPAD + k0 + t + 4];
            mma_tf32(acc[0][an], a[0][0], a[0][1], a[0][2], a[0][3], b0, b1);
            mma_tf32(acc[1][an], a[1][0], a[1][1], a[1][2], a[1][3], b0, b1);
        }
    }

#pragma unroll
    for (int am = 0; am < 2; am++) {
        int r0 = wid * 32 + am * 16 + g;
        int n0 = base + r0, n1 = base + r0 + 8;
#pragma unroll
        for (int an = 0; an < 8; an++) {
            int c = an * 8 + 2 * t;
            if (n0 < NN) {
                float2 v = make_float2(acc[am][an][0], acc[am][an][1]);
                *reinterpret_cast<float2*>(&g_h [n0 * HH + c]) = v;
                *reinterpret_cast<float2*>(&g_h0[n0 * HH + c]) = v;
            }
            if (n1 < NN) {
                float2 v = make_float2(acc[am][an][2], acc[am][an][3]);
                *reinterpret_cast<float2*>(&g_h [n1 * HH + c]) = v;
                *reinterpret_cast<float2*>(&g_h0[n1 * HH + c]) = v;
            }
        }
    }
}

// ---------------- prologue A: degree count for all 4 edge sets ------------
__global__ void k_deg(const int* __restrict__ d0, const int* __restrict__ d1,
                      const int* __restrict__ d2, const int* __restrict__ d3) {
    int e = blockIdx.x * 256 + threadIdx.x;
    if (e >= EE) return;
    int j = blockIdx.y;
    const int* d = (j == 0) ? d0 : (j == 1) ? d1 : (j == 2) ? d2 : d3;
    atomicAdd(&g_deg4[j * NN + d[e]], 1);
}

// ---------------- prologue: 2-level exclusive scan of deg -> rowptr -------
__global__ void k_scanA() {              // grid (SCB, 4), 1024 threads
    __shared__ int tmp[1024];
    int j = blockIdx.y;
    int gid = blockIdx.x * 1024 + threadIdx.x;
    int v = (gid < NN) ? g_deg4[j * NN + gid] : 0;
    tmp[threadIdx.x] = v; __syncthreads();
    for (int off = 1; off < 1024; off <<= 1) {
        int x = (threadIdx.x >= off) ? tmp[threadIdx.x - off] : 0;
        __syncthreads();
        tmp[threadIdx.x] += x;
        __syncthreads();
    }
    if (gid < NN) g_iscan[j * NN + gid] = tmp[threadIdx.x];
    if (threadIdx.x == 1023) g_bsum[j * SCB + blockIdx.x] = tmp[1023];
}

__global__ void k_scanB() {              // grid (4), 128 threads
    __shared__ int tmp[128];
    int j = blockIdx.x;
    int v = (threadIdx.x < SCB) ? g_bsum[j * SCB + threadIdx.x] : 0;
    tmp[threadIdx.x] = v; __syncthreads();
    for (int off = 1; off < 128; off <<= 1) {
        int x = (threadIdx.x >= off) ? tmp[threadIdx.x - off] : 0;
        __syncthreads();
        tmp[threadIdx.x] += x;
        __syncthreads();
    }
    if (threadIdx.x < SCB) g_boff[j * SCB + threadIdx.x] = tmp[threadIdx.x] - v;
}

__global__ void k_scanC() {              // grid (SCB, 4), 1024 threads
    int j = blockIdx.y;
    int gid = blockIdx.x * 1024 + threadIdx.x;
    if (gid < NN) {
        int ex = g_iscan[j * NN + gid] - g_deg4[j * NN + gid]
               + g_boff[j * SCB + blockIdx.x];
        g_rowptr4[j * (NN + 1) + gid] = ex;
        g_cur4[j * NN + gid] = ex;
        if (gid == NN - 1) g_rowptr4[j * (NN + 1) + NN] = EE;
    }
}

// ---------------- prologue: bin edges by dst (CSR) ------------------------
__global__ void k_binE(const int* __restrict__ s0, const int* __restrict__ s1,
                       const int* __restrict__ s2, const int* __restrict__ s3) {
    int e = blockIdx.x * 256 + threadIdx.x;
    if (e >= EE) return;
    int j = blockIdx.y;
    const int* sp = (j == 0) ? s0 : (j == 1) ? s1 : (j == 2) ? s2 : s3;
    int d = sp[EE + e];                  // dst row of the (2,E) tensor
    int s = sp[e];                       // src row
    int pos = atomicAdd(&g_cur4[j * NN + d], 1);
    g_ssrc4[j * EE + pos] = s;
}

// ---------------- prologue B: bucket lists for all 4 edge sets ------------
__global__ void k_fill4() {
    __shared__ int scnt[NBUK], sbase[NBUK], scur[NBUK];
    int t = threadIdx.x;
    int j = blockIdx.y;
    if (t < NBUK) { scnt[t] = 0; scur[t] = 0; }
    __syncthreads();
    int i = blockIdx.x * 256 + t;
    int b = -1;
    if (i < NN) {
        int d = g_deg4[j * NN + i];
        b = d < NBUK - 1 ? d : NBUK - 1;
        atomicAdd(&scnt[b], 1);
    }
    __syncthreads();
    if (t < NBUK && scnt[t] > 0) sbase[t] = atomicAdd(&g_cnt4[j * NBUK + t], scnt[t]);
    __syncthreads();
    if (i < NN) {
        int pos = atomicAdd(&scur[b], 1);
        g_list4[(j * NBUK + b) * NN + sbase[b] + pos] = i;
    }
}

// ---------------- K2: gather segment-sum  hs[d] = sum_{e in seg(d)} h[src] -
__global__ void k_gather(int j) {
    int d = (blockIdx.x * 256 + threadIdx.x) >> 5;
    if (d >= NN) return;
    int lane = threadIdx.x & 31;
    const int* rp = g_rowptr4 + j * (NN + 1);
    int beg = rp[d], end = rp[d + 1];
    if (beg == end) return;              // deg==0: hs never read (bucket 0)
    const int* ss = g_ssrc4 + j * EE;
    float2 acc = make_float2(0.f, 0.f);
    int e = beg;
    for (; e + 4 <= end; e += 4) {
        int s0 = ss[e], s1 = ss[e+1], s2 = ss[e+2], s3 = ss[e+3];
        float2 v0 = *reinterpret_cast<const float2*>(&g_h[s0 * HH + lane * 2]);
        float2 v1 = *reinterpret_cast<const float2*>(&g_h[s1 * HH + lane * 2]);
        float2 v2 = *reinterpret_cast<const float2*>(&g_h[s2 * HH + lane * 2]);
        float2 v3 = *reinterpret_cast<const float2*>(&g_h[s3 * HH + lane * 2]);
        acc.x += (v0.x + v1.x) + (v2.x + v3.x);
        acc.y += (v0.y + v1.y) + (v2.y + v3.y);
    }
    for (; e < end; e++) {
        int s = ss[e];
        float2 v = *reinterpret_cast<const float2*>(&g_h[s * HH + lane * 2]);
        acc.x += v.x; acc.y += v.y;
    }
    *reinterpret_cast<float2*>(&g_hs[d * HH + lane * 2]) = acc;
}

// ---------------- K6: bucketed apply via tf32 MMA -------------------------
// out = [hs;h] @ [wl;wr] + bl per bucket chunk: M=128 nodes, K=128, N=64.
// 4 warps, warp tile 32x64 = 2x8 m16n8k8 atoms, 16 k-steps.
#define KPAD 132  // K=128 + pad 4
#define APPLY_SMEM ((128 * KPAD + HH * KPAD + HH) * 4)
#define AGRID 832

__global__ void __launch_bounds__(128, 2)
k_apply(const float* __restrict__ wl_base,
        const float* __restrict__ bl_base,
        const float* __restrict__ wr_base,
        int relu, int j) {
    // derive (bucket, chunk) from blockIdx by walking the 21 bucket counts
    int b = -1, chunk0 = 0, cnt = 0;
    {
        int rem = blockIdx.x;
        for (int bb = 0; bb < NBUK; bb++) {
            int c = g_cnt4[j * NBUK + bb];
            int nch = (c + NPB - 1) >> 7;
            if (rem < nch) { b = bb; chunk0 = rem * NPB; cnt = c; break; }
            rem -= nch;
        }
    }
    if (b < 0) return;
    const int* list = g_list4 + (j * NBUK + b) * NN + chunk0;
    int nv = cnt - chunk0; if (nv > NPB) nv = NPB;
    int tid = threadIdx.x;

    if (b == 0) {                       // deg==0: h unchanged, relu still applies
        if (!relu) return;
        for (int idx = tid; idx < nv * 16; idx += 128) {
            int n = list[idx >> 4];
            int c = (idx & 15) * 4;
            float4* p = reinterpret_cast<float4*>(&g_h[n * HH + c]);
            float4 v = *p;
            v.x = fmaxf(v.x, 0.f); v.y = fmaxf(v.y, 0.f);
            v.z = fmaxf(v.z, 0.f); v.w = fmaxf(v.w, 0.f);
            *p = v;
        }
        return;
    }

    extern __shared__ float sm[];
    float* sA  = sm;                     // [m=0..127][k=0..127]  (tf32 bits)
    float* sW  = sm + 128 * KPAD;        // [n=0..63][k=0..127]   (tf32 bits)
    float* sBL = sm + 128 * KPAD + HH * KPAD;

    const float* wl = wl_base + b * HH * HH;
    const float* wr = wr_base + b * HH * HH;
    const float* bl = bl_base + b * HH;

    // stage weights transposed: sW[n][k] = wl[k][n] (k<64) / wr[k-64][n]
    for (int i = tid; i < HH * HH; i += 128) {
        int k = i >> 6, n = i & 63;
        sW[n * KPAD + k]      = cvt_tf32(wl[i]);
        sW[n * KPAD + 64 + k] = cvt_tf32(wr[i]);
    }
    if (tid < HH) sBL[tid] = bl[tid];

    // stage activations row-major: sA[m][k] = hs[node][k] (k<64), h (k>=64)
    {
        int m = tid;
        int node = (m < nv) ? list[m] : -1;
        float* row = sA + m * KPAD;
        if (node >= 0) {
            const float4* ha = reinterpret_cast<const float4*>(&g_hs[node * HH]);
            const float4* hb = reinterpret_cast<const float4*>(&g_h [node * HH]);
#pragma unroll
            for (int q = 0; q < 16; q++) {
                *reinterpret_cast<float4*>(row + q * 4)      = cvt_tf32_v4(ha[q]);
                *reinterpret_cast<float4*>(row + 64 + q * 4) = cvt_tf32_v4(hb[q]);
            }
        } else {
#pragma unroll
            for (int q = 0; q < 32; q++)
                *reinterpret_cast<float4*>(row + q * 4) = make_float4(0,0,0,0);
        }
    }
    __syncthreads();

    int lane = tid & 31, wid = tid >> 5;
    int g = lane >> 2, t = lane & 3;

    float acc[2][8][4];
#pragma unroll
    for (int am = 0; am < 2; am++)
#pragma unroll
        for (int an = 0; an < 8; an++) {
            float b0 = sBL[an * 8 + 2 * t], b1 = sBL[an * 8 + 2 * t + 1];
            acc[am][an][0] = b0; acc[am][an][1] = b1;
            acc[am][an][2] = b0; acc[am][an][3] = b1;
        }

    const unsigned* uA = reinterpret_cast<const unsigned*>(sA);
    const unsigned* uW = reinterpret_cast<const unsigned*>(sW);
#pragma unroll 4
    for (int ks = 0; ks < 16; ks++) {
        int k0 = ks * 8;
        unsigned a[2][4];
#pragma unroll
        for (int am = 0; am < 2; am++) {
            int mr = wid * 32 + am * 16 + g;
            a[am][0] = uA[mr * KPAD + k0 + t];
            a[am][1] = uA[(mr + 8) * KPAD + k0 + t];
            a[am][2] = uA[mr * KPAD + k0 + t + 4];
            a[am][3] = uA[(mr + 8) * KPAD + k0 + t + 4];
        }
#pragma unroll
        for (int an = 0; an < 8; an++) {
            unsigned b0 = uW[(an * 8 + g) * KPAD + k0 + t];
            unsigned b1 = uW[(an * 8 + g) * KPAD + k0 + t + 4];
            mma_tf32(acc[0][an], a[0][0], a[0][1], a[0][2], a[0][3], b0, b1);
            mma_tf32(acc[1][an], a[1][0], a[1][1], a[1][2], a[1][3], b0, b1);
        }
    }

    // epilogue: rows r, r+8 per atom; cols an*8 + 2t, +1
#pragma unroll
    for (int am = 0; am < 2; am++) {
        int r0 = wid * 32 + am * 16 + g;
        int r1 = r0 + 8;
        int n0 = (r0 < nv) ? list[r0] : -1;
        int n1 = (r1 < nv) ? list[r1] : -1;
#pragma unroll
        for (int an = 0; an < 8; an++) {
            int c = an * 8 + 2 * t;
            if (n0 >= 0) {
                float2 v = make_float2(acc[am][an][0], acc[am][an][1]);
                if (relu) { v.x = fmaxf(v.x, 0.f); v.y = fmaxf(v.y, 0.f); }
                *reinterpret_cast<float2*>(&g_h[n0 * HH + c]) = v;
            }
            if (n1 >= 0) {
                float2 v = make_float2(acc[am][an][2], acc[am][an][3]);
                if (relu) { v.x = fmaxf(v.x, 0.f); v.y = fmaxf(v.y, 0.f); }
                *reinterpret_cast<float2*>(&g_h[n1 * HH + c]) = v;
            }
        }
    }
}

// ---------------- K7: LayerNorm + residual --------------------------------
__global__ void k_ln(const float* __restrict__ g, const float* __restrict__ bb) {
    int wid = (blockIdx.x * 256 + threadIdx.x) >> 5;
    int lane = threadIdx.x & 31;
    if (wid >= NN) return;
    const float* hp = g_h + wid * HH;
    float v0 = hp[lane], v1 = hp[lane + 32];
    float s = v0 + v1;
#pragma unroll
    for (int o = 16; o > 0; o >>= 1) s += __shfl_xor_sync(0xffffffffu, s, o);
    float mu = s * (1.f / 64.f);
    float d0 = v0 - mu, d1 = v1 - mu;
    float q = d0 * d0 + d1 * d1;
#pragma unroll
    for (int o = 16; o > 0; o >>= 1) q += __shfl_xor_sync(0xffffffffu, q, o);
    float rstd = rsqrtf(q * (1.f / 64.f) + LN_EPS);
    const float* h0p = g_h0 + wid * HH;
    g_h[wid*HH + lane]      = d0 * rstd * g[lane]      + bb[lane]      + h0p[lane];
    g_h[wid*HH + lane + 32] = d1 * rstd * g[lane + 32] + bb[lane + 32] + h0p[lane + 32];
}

// ---------------- K8: pooled[batch[i]] += h[i] for ground nodes (i<G) -----
__global__ void k_pool(const int* __restrict__ batch_idx) {
    int t = blockIdx.x * 256 + threadIdx.x;
    int i = t >> 4;
    if (i >= GG) return;
    int c = (t & 15) * 4;
    int gidx = batch_idx[i];
    float4 v = *reinterpret_cast<const float4*>(&g_h[i * HH + c]);
    red_add_v4(&g_pooled[gidx * HH + c], v);
}

// ---------------- K9: out = pooled @ out_w + out_b ------------------------
__global__ void k_out(const float* __restrict__ ow, const float* __restrict__ ob,
                      float* __restrict__ out) {
    int gidx = threadIdx.x;           // 128 threads
    float acc = ob[0];
#pragma unroll
    for (int k = 0; k < HH; k++) acc += g_pooled[gidx * HH + k] * ow[k];
    out[gidx] = acc;
}

// ---------------- host launcher ------------------------------------------
extern "C" void kernel_launch(void* const* d_in, const int* in_sizes, int n_in,
                              void* d_out, int out_size) {
    (void)in_sizes; (void)n_in; (void)out_size;
    const float* x        = (const float*)d_in[0];
    // reference edge-set order: edge_index, node_subnode, subgraph_edge, subnode_node
    const int* eis[4] = { (const int*)d_in[1], (const int*)d_in[3],
                          (const int*)d_in[2], (const int*)d_in[4] };
    const int*   batch_idx = (const int*)d_in[7];
    const float* emb_w  = (const float*)d_in[8];
    const float* emb_b  = (const float*)d_in[9];
    const float* conv_wl = (const float*)d_in[10];
    const float* conv_bl = (const float*)d_in[11];
    const float* conv_wr = (const float*)d_in[12];
    const float* ln_g   = (const float*)d_in[13];
    const float* ln_b   = (const float*)d_in[14];
    const float* out_w  = (const float*)d_in[15];
    const float* out_b  = (const float*)d_in[16];
    float* out = (float*)d_out;

    cudaFuncSetAttribute(k_apply, cudaFuncAttributeMaxDynamicSharedMemorySize,
                         APPLY_SMEM);

    // ---- prologue: structure-only CSR + bucketing (all 4 edge sets) ----
    k_zero<<<(4 * NN + 255) / 256, 256>>>();
    {
        dim3 gd((EE + 255) / 256, 4);
        k_deg<<<gd, 256>>>(eis[0] + EE, eis[1] + EE, eis[2] + EE, eis[3] + EE);
        dim3 gs(SCB, 4);
        k_scanA<<<gs, 1024>>>();
        k_scanB<<<4, 128>>>();
        k_scanC<<<gs, 1024>>>();
        k_binE<<<gd, 256>>>(eis[0], eis[1], eis[2], eis[3]);
        dim3 gf((NN + 255) / 256, 4);
        k_fill4<<<gf, 256>>>();
    }

    k_embed<<<(NN + 127) / 128, 128>>>(x, emb_w, emb_b);

    for (int j = 0; j < 4; j++) {
        k_gather<<<(NN * 32 + 255) / 256, 256>>>(j);
        k_apply<<<AGRID, 128, APPLY_SMEM>>>(conv_wl + j * NBUK * HH * HH,
                                            conv_bl + j * NBUK * HH,
                                            conv_wr + j * NBUK * HH * HH,
                                            (j < 3) ? 1 : 0, j);
    }

    k_ln<<<(NN * 32 + 255) / 256, 256>>>(ln_g, ln_b);
    k_pool<<<(GG * 16 + 255) / 256, 256>>>(batch_idx);
    k_out<<<1, NGRAPH>>>(out_w, out_b, out);
}